// round 1
// baseline (speedup 1.0000x reference)
#include <cuda_runtime.h>
#include <math.h>

#define BATCH   4
#define CCH     128
#define HH      14
#define WW      14
#define SP      (HH*WW)        // 196
#define NPIX    (BATCH*SP)     // 784
#define NPROTO  2000
#define NCLS    200
#define IMG     224
#define UPF4    (IMG/4)        // 56
#define UPSZ    (IMG*IMG)      // 50176

// ---------------- scratch (no allocations allowed) ----------------
__device__ __align__(16) float g_f[NPIX*CCH];       // sigmoid features, pixel-major
__device__ __align__(16) float g_f2[NPIX];          // ||f||^2 per pixel
__device__ __align__(16) float g_p2[NPROTO];        // ||proto||^2
__device__ __align__(16) float g_dist[BATCH*NPROTO*SP];   // 6.27 MB, L2-resident
__device__ __align__(16) float g_acts[BATCH*NPROTO];      // log activations

// ---------------- kernel 1: add-on layers (1x1 conv -> relu -> 1x1 conv -> sigmoid) ----
// 4 pixels per block, 128 threads (thread = output channel). Weight register reused
// across the 4 pixels -> 4x less w traffic.
__global__ void addon_kernel(const float* __restrict__ fmap,
                             const float* __restrict__ w1, const float* __restrict__ b1,
                             const float* __restrict__ w2, const float* __restrict__ b2) {
    const int pix0 = blockIdx.x * 4;
    const int t = threadIdx.x;   // channel 0..127
    __shared__ float xs[4][CCH];
    __shared__ float hs[4][CCH];
    __shared__ float red[CCH];

    #pragma unroll
    for (int px = 0; px < 4; px++) {
        int pix = pix0 + px;
        int b = pix / SP, s = pix % SP;
        xs[px][t] = fmap[(b*CCH + t)*SP + s];
    }
    __syncthreads();

    float acc[4];
    {
        float bias = b1[t];
        #pragma unroll
        for (int px = 0; px < 4; px++) acc[px] = bias;
        const float* wrow = &w1[t*CCH];
        #pragma unroll 4
        for (int c = 0; c < CCH; c++) {
            float wv = wrow[c];
            #pragma unroll
            for (int px = 0; px < 4; px++) acc[px] = fmaf(wv, xs[px][c], acc[px]);
        }
    }
    #pragma unroll
    for (int px = 0; px < 4; px++) hs[px][t] = fmaxf(acc[px], 0.0f);
    __syncthreads();

    float fv[4];
    {
        float bias = b2[t];
        #pragma unroll
        for (int px = 0; px < 4; px++) acc[px] = bias;
        const float* wrow = &w2[t*CCH];
        #pragma unroll 4
        for (int c = 0; c < CCH; c++) {
            float wv = wrow[c];
            #pragma unroll
            for (int px = 0; px < 4; px++) acc[px] = fmaf(wv, hs[px][c], acc[px]);
        }
        #pragma unroll
        for (int px = 0; px < 4; px++) {
            fv[px] = 1.0f / (1.0f + expf(-acc[px]));
            g_f[(pix0 + px)*CCH + t] = fv[px];
        }
    }

    // ||f||^2 per pixel
    for (int px = 0; px < 4; px++) {
        __syncthreads();
        red[t] = fv[px] * fv[px];
        __syncthreads();
        #pragma unroll
        for (int off = 64; off > 0; off >>= 1) {
            if (t < off) red[t] += red[t + off];
            __syncthreads();
        }
        if (t == 0) g_f2[pix0 + px] = red[0];
    }
}

// ---------------- kernel 2: ||p||^2 ----------------
__global__ void p2_kernel(const float* __restrict__ protos) {
    int p = blockIdx.x * 8 + (threadIdx.x >> 5);
    int lane = threadIdx.x & 31;
    if (p >= NPROTO) return;
    float s = 0.0f;
    #pragma unroll
    for (int c = lane; c < CCH; c += 32) {
        float v = protos[p*CCH + c];
        s = fmaf(v, v, s);
    }
    #pragma unroll
    for (int o = 16; o > 0; o >>= 1) s += __shfl_xor_sync(0xFFFFFFFFu, s, o);
    if (lane == 0) g_p2[p] = s;
}

// ---------------- kernel 3: distance GEMM + sqrt epilogue ----------------
// M = 784 pixels, N = 2000 protos, K = 128. 64x64 tile, 16x16 threads, 4x4 micro.
#define BM 64
#define BN 64
#define BK 32
__global__ void dist_kernel(const float* __restrict__ protos) {
    __shared__ float As[BK][BM + 4];
    __shared__ float Bs[BK][BN + 4];
    const int tid = threadIdx.x;           // 256
    const int tx = tid & 15, ty = tid >> 4;
    const int m0 = blockIdx.y * BM;
    const int n0 = blockIdx.x * BN;

    float acc[4][4] = {};

    for (int k0 = 0; k0 < CCH; k0 += BK) {
        #pragma unroll
        for (int l = 0; l < 2; l++) {
            int idx = tid + l*256;         // 0..511
            int row = idx >> 3;            // 0..63
            int kc4 = idx & 7;             // float4 within BK
            float4 v = make_float4(0,0,0,0);
            int m = m0 + row;
            if (m < NPIX) v = *(const float4*)&g_f[m*CCH + k0 + kc4*4];
            As[kc4*4+0][row] = v.x; As[kc4*4+1][row] = v.y;
            As[kc4*4+2][row] = v.z; As[kc4*4+3][row] = v.w;
            float4 u = make_float4(0,0,0,0);
            int n = n0 + row;
            if (n < NPROTO) u = *(const float4*)&protos[n*CCH + k0 + kc4*4];
            Bs[kc4*4+0][row] = u.x; Bs[kc4*4+1][row] = u.y;
            Bs[kc4*4+2][row] = u.z; Bs[kc4*4+3][row] = u.w;
        }
        __syncthreads();
        #pragma unroll
        for (int k = 0; k < BK; k++) {
            float4 a4 = *(const float4*)&As[k][ty*4];
            float4 b4 = *(const float4*)&Bs[k][tx*4];
            float a[4] = {a4.x, a4.y, a4.z, a4.w};
            float bb[4] = {b4.x, b4.y, b4.z, b4.w};
            #pragma unroll
            for (int i = 0; i < 4; i++)
                #pragma unroll
                for (int j = 0; j < 4; j++)
                    acc[i][j] = fmaf(a[i], bb[j], acc[i][j]);
        }
        __syncthreads();
    }

    #pragma unroll
    for (int i = 0; i < 4; i++) {
        int m = m0 + ty*4 + i;
        if (m >= NPIX) continue;
        int b = m / SP, s = m % SP;
        float f2 = g_f2[m];
        #pragma unroll
        for (int j = 0; j < 4; j++) {
            int n = n0 + tx*4 + j;
            if (n >= NPROTO) continue;
            float d2 = f2 + g_p2[n] - 2.0f*acc[i][j];
            d2 = fmaxf(d2, 0.0f);
            g_dist[(b*NPROTO + n)*SP + s] = sqrtf(d2 + 1e-12f);
        }
    }
}

// ---------------- kernel 4: bilinear x16 upsample + write up + global min + act ----
// One block per (b,p). Separable: horizontal-interp rows in smem, then vertical
// interp with float4 streaming stores (fully contiguous per (b,p) plane).
__device__ __forceinline__ void bil_coef(int o, int lim, int& ia, int& ib, float& w) {
    int r = o & 15, q = o >> 4;
    int i0;
    if (r >= 8) { i0 = q;     w = (float)(r - 8) * 0.0625f + 0.03125f; }
    else        { i0 = q - 1; w = (float)(r + 8) * 0.0625f + 0.03125f; }
    ia = i0 < 0 ? 0 : i0;
    ib = (i0 + 1 > lim) ? lim : i0 + 1;
}

__global__ void upsample_kernel(float* __restrict__ up, float* __restrict__ out_min) {
    const int bp = blockIdx.x;                 // b*NPROTO + p
    const int t = threadIdx.x;                 // 256
    __shared__ float src[SP];
    __shared__ __align__(16) float hrow[HH][IMG];   // 12.25 KB
    __shared__ float red[256];

    if (t < SP) src[t] = g_dist[bp*SP + t];
    __syncthreads();

    // horizontal interpolation: 14 rows x 224
    for (int i = t; i < HH*IMG; i += 256) {
        int row = i / IMG, x = i - row*IMG;
        int xa, xb; float w;
        bil_coef(x, WW - 1, xa, xb, w);
        hrow[row][x] = (1.0f - w)*src[row*WW + xa] + w*src[row*WW + xb];
    }
    __syncthreads();

    float mn = INFINITY;
    float* dst = up + (size_t)bp * UPSZ;
    // 224 rows x 56 float4 = 12544 float4, contiguous in v
    for (int v = t; v < IMG*UPF4; v += 256) {
        int y = v / UPF4, xv = (v - y*UPF4) * 4;
        int ya, yb; float w;
        bil_coef(y, HH - 1, ya, yb, w);
        float4 A = *(const float4*)&hrow[ya][xv];
        float4 B = *(const float4*)&hrow[yb][xv];
        float4 o;
        float wi = 1.0f - w;
        o.x = wi*A.x + w*B.x;
        o.y = wi*A.y + w*B.y;
        o.z = wi*A.z + w*B.z;
        o.w = wi*A.w + w*B.w;
        mn = fminf(mn, fminf(fminf(o.x, o.y), fminf(o.z, o.w)));
        __stcs((float4*)&dst[(size_t)v*4], o);
    }

    red[t] = mn;
    __syncthreads();
    #pragma unroll
    for (int off = 128; off > 0; off >>= 1) {
        if (t < off) red[t] = fminf(red[t], red[t + off]);
        __syncthreads();
    }
    if (t == 0) {
        float m = red[0];
        out_min[bp] = m;
        g_acts[bp] = logf((m + 1.0f) / (m + 1e-4f));
    }
}

// ---------------- kernel 5: logits = acts @ last_w^T ----------------
__global__ void logits_kernel(const float* __restrict__ last_w, float* __restrict__ out) {
    const int cls = blockIdx.x;
    const int b = blockIdx.y;
    const int t = threadIdx.x;        // 256
    __shared__ float red[8];
    const float* a = &g_acts[b*NPROTO];
    const float* wr = &last_w[cls*NPROTO];
    float s = 0.0f;
    for (int p = t; p < NPROTO; p += 256) s = fmaf(a[p], wr[p], s);
    #pragma unroll
    for (int o = 16; o > 0; o >>= 1) s += __shfl_xor_sync(0xFFFFFFFFu, s, o);
    if ((t & 31) == 0) red[t >> 5] = s;
    __syncthreads();
    if (t == 0) {
        float tot = 0.0f;
        #pragma unroll
        for (int w = 0; w < 8; w++) tot += red[w];
        out[b*NCLS + cls] = tot;
    }
}

// ---------------- launch ----------------
extern "C" void kernel_launch(void* const* d_in, const int* in_sizes, int n_in,
                              void* d_out, int out_size) {
    const float* fmap   = (const float*)d_in[0];
    const float* w1     = (const float*)d_in[1];
    const float* b1     = (const float*)d_in[2];
    const float* w2     = (const float*)d_in[3];
    const float* b2     = (const float*)d_in[4];
    const float* protos = (const float*)d_in[5];
    const float* last_w = (const float*)d_in[6];

    float* out        = (float*)d_out;
    float* out_logits = out;                               // 4*200
    float* out_min    = out + BATCH*NCLS;                  // 4*2000
    float* out_up     = out + BATCH*NCLS + BATCH*NPROTO;   // 4*2000*224*224

    addon_kernel<<<NPIX/4, CCH>>>(fmap, w1, b1, w2, b2);
    p2_kernel<<<(NPROTO + 7)/8, 256>>>(protos);
    dist_kernel<<<dim3((NPROTO + BN - 1)/BN, (NPIX + BM - 1)/BM), 256>>>(protos);
    upsample_kernel<<<BATCH*NPROTO, 256>>>(out_up, out_min);
    logits_kernel<<<dim3(NCLS, BATCH), 256>>>(last_w, out_logits);
}